// round 12
// baseline (speedup 1.0000x reference)
#include <cuda_runtime.h>
#include <math.h>

typedef unsigned long long ull;

// ---------------------------------------------------------------------------
// MAPHead: probe-attention pooling + MLP. N=32, L=4096, D=768, H=12, MLP=3072.
//   logits[n,h,l] = x[n,l,:] . wkq[:,h]      (pass 1, f32x2 head pairs, 4-row
//                                             blocking; bk.q const dropped:
//                                             softmax-invariant)
//   k_logits emits per-chunk (m,sumexp)      (fused normalizer)
//   xbar[n,h,:] = sum_l softmax * x[n,l,:]   (pass 2, f32x2, 2 cols/thread)
//   o -> xa+LN (fused) -> MLP on [32,768]    (epilogue GEMVs, mlp2 K-split)
// ---------------------------------------------------------------------------

#define NB   32
#define LSEQ 4096
#define DM   768
#define NH   12
#define DH   64
#define MLPD 3072
#define NCH  16                 // 256-row chunks (pass 1 & 2)

__device__ __forceinline__ ull pk2(float a, float b) {
    ull r; asm("mov.b64 %0,{%1,%2};" : "=l"(r) : "f"(a), "f"(b)); return r;
}
__device__ __forceinline__ void up2(ull v, float& a, float& b) {
    asm("mov.b64 {%0,%1},%2;" : "=f"(a), "=f"(b) : "l"(v));
}
__device__ __forceinline__ void fma2(ull& acc, ull a, ull b) {
    asm("fma.rn.f32x2 %0,%1,%2,%0;" : "+l"(acc) : "l"(a), "l"(b));
}
__device__ __forceinline__ ull add2(ull a, ull b) {
    ull r; asm("add.rn.f32x2 %0,%1,%2;" : "=l"(r) : "l"(a), "l"(b)); return r;
}

// ------------------------------ scratch -------------------------------------
__device__ float  g_qp[4*DM];                         // probe@wq d-slice partials
__device__ float  g_qvec[NH*DH];
__device__ float2 g_wkq2[6*DM];                       // [hp][d] head pairs
__device__ float  g_logits[(size_t)NB*NH*LSEQ];
__device__ float2 g_cms[NB*NCH*NH];                   // per-chunk (m, sumexp)
__device__ ull    g_part[(size_t)NB*NCH*NH*(DM/2)];   // chunk partial xbar
__device__ float  g_xbar[NB*NH*DM];
__device__ float  g_o[NB*NH*DH];
__device__ float  g_xa[NB*DM];
__device__ float  g_y[NB*DM];
__device__ float  g_h1[NB*MLPD];
__device__ float  g_mp[4*NB*DM];                      // mlp2 K-split partials

// ------------------------------ prep 1a: qp[s][he] = probe_s . wq_s ----------
// grid 4 (d-slices of 192), block 768 (he). wq[d*768+he]: coalesced.
__global__ void k_qp(const float* __restrict__ probe,
                     const float* __restrict__ wq) {
    __shared__ float ps[192];
    int s = blockIdx.x, t = threadIdx.x;
    if (t < 192) ps[t] = probe[s*192 + t];
    __syncthreads();
    float acc = 0.f;
    const float* wp = wq + (size_t)(s*192)*(NH*DH) + t;
    #pragma unroll 8
    for (int d = 0; d < 192; ++d) acc = fmaf(ps[d], wp[(size_t)d*(NH*DH)], acc);
    g_qp[s*DM + t] = acc;
}

// ------------------------------ prep 1b: qvec = (sum qp + bq)/8 --------------
__global__ void k_qc(const float* __restrict__ bq) {
    int he = threadIdx.x;
    g_qvec[he] = (g_qp[he] + g_qp[DM + he] + g_qp[2*DM + he] + g_qp[3*DM + he]
                  + bq[he]) * 0.125f;
}

// ------------------------------ prep 2: wkq (head-pair packed) ---------------
__global__ void prep_wkq(const float* __restrict__ wk) {
    int idx = blockIdx.x*256 + threadIdx.x;
    if (idx < NH*DM) {
        int d = idx / NH, h = idx - d*NH;
        float acc = 0.f;
        const float* w = wk + (size_t)d*(NH*DH) + h*DH;
        const float* q = g_qvec + h*DH;
        #pragma unroll
        for (int e = 0; e < DH; ++e) acc = fmaf(w[e], q[e], acc);
        ((float*)g_wkq2)[(((h>>1)*DM) + d)*2 + (h&1)] = acc;
    }
}

// ------------------------------ pass 1: logits + chunk (m,s) -----------------
// grid (NCH, NB), block 256 (8 warps). Warp: 32 rows, 4 at a time. Per 32-col
// block: 4 LDG.32 + 4 pack + 6 LDS.64 + 24 FMA2 -> LDS traffic halved vs 2-row.
// acc[4][6] = 48 regs; lean staging; 3 CTAs/SM target.
__global__ void __launch_bounds__(256, 3)
k_logits(const float* __restrict__ x) {
    __shared__ float2 wks[6*DM];     // 36 KB
    const int t = threadIdx.x, lane = t & 31, w = t >> 5;
    const int n = blockIdx.y;
    const int row0 = blockIdx.x*256 + w*32;

    for (int i = t; i < 6*DM/2; i += 256)
        ((float4*)wks)[i] = ((const float4*)g_wkq2)[i];
    __syncthreads();

    for (int rb = 0; rb < 32; rb += 4) {
        const float* xr = x + ((size_t)n*LSEQ + row0 + rb)*DM + lane;
        ull a0[6], a1[6], a2[6], a3[6];
        #pragma unroll
        for (int hp = 0; hp < 6; ++hp) {
            a0[hp] = 0ULL; a1[hp] = 0ULL; a2[hp] = 0ULL; a3[hp] = 0ULL;
        }

        #pragma unroll 2
        for (int j = 0; j < 24; ++j) {
            float u0 = xr[j*32];
            float u1 = xr[j*32 +   DM];
            float u2 = xr[j*32 + 2*DM];
            float u3 = xr[j*32 + 3*DM];
            ull U0 = pk2(u0, u0), U1 = pk2(u1, u1);
            ull U2 = pk2(u2, u2), U3 = pk2(u3, u3);
            #pragma unroll
            for (int hp = 0; hp < 6; ++hp) {
                ull wv = *(const ull*)(wks + hp*DM + j*32 + lane);
                fma2(a0[hp], U0, wv);
                fma2(a1[hp], U1, wv);
                fma2(a2[hp], U2, wv);
                fma2(a3[hp], U3, wv);
            }
        }

        // packed butterfly reduce
        #pragma unroll
        for (int off = 16; off; off >>= 1)
            #pragma unroll
            for (int hp = 0; hp < 6; ++hp) {
                a0[hp] = add2(a0[hp], __shfl_xor_sync(0xffffffffu, a0[hp], off));
                a1[hp] = add2(a1[hp], __shfl_xor_sync(0xffffffffu, a1[hp], off));
                a2[hp] = add2(a2[hp], __shfl_xor_sync(0xffffffffu, a2[hp], off));
                a3[hp] = add2(a3[hp], __shfl_xor_sync(0xffffffffu, a3[hp], off));
            }

        if (lane < 4) {
            int l = row0 + rb + lane;
            float fr[NH];
            #pragma unroll
            for (int hp = 0; hp < 6; ++hp) {
                ull a = (lane == 0) ? a0[hp] : (lane == 1) ? a1[hp]
                      : (lane == 2) ? a2[hp] : a3[hp];
                up2(a, fr[2*hp], fr[2*hp+1]);
            }
            #pragma unroll
            for (int h = 0; h < NH; ++h)
                g_logits[((size_t)n*NH + h)*LSEQ + l] = fr[h];
        }
    }

    // tail: per-chunk (m, sumexp) per head from just-written logits (L2-hot)
    __syncthreads();
    if (t < NH) {
        const float* lp = g_logits + ((size_t)n*NH + t)*LSEQ + blockIdx.x*256;
        float m = -1e30f;
        #pragma unroll 8
        for (int r = 0; r < 256; ++r) m = fmaxf(m, lp[r]);
        float s = 0.f;
        #pragma unroll 8
        for (int r = 0; r < 256; ++r) s += __expf(lp[r] - m);
        g_cms[((size_t)n*NCH + blockIdx.x)*NH + t] = make_float2(m, s);
    }
}

// ------------------------------ pass 2: xbar (frozen) ------------------------
__global__ void __launch_bounds__(384)
k_xbar(const float* __restrict__ x) {
    __shared__ ull   p2s[NH*256];    // 24 KB
    __shared__ float Ms[NH], Is[NH];
    const int t = threadIdx.x, s = blockIdx.x, n = blockIdx.y;

    if (t < NH) {
        float M = -1e30f;
        #pragma unroll
        for (int c = 0; c < NCH; ++c)
            M = fmaxf(M, g_cms[((size_t)n*NCH + c)*NH + t].x);
        float S = 0.f;
        #pragma unroll
        for (int c = 0; c < NCH; ++c) {
            float2 ms = g_cms[((size_t)n*NCH + c)*NH + t];
            S += __expf(ms.x - M) * ms.y;
        }
        Ms[t] = M; Is[t] = 1.f / S;
    }
    __syncthreads();

    for (int i = t; i < NH*256; i += 384) {
        int h = i >> 8, r = i & 255;
        float lg = g_logits[((size_t)n*NH + h)*LSEQ + s*256 + r];
        float p = __expf(lg - Ms[h]) * Is[h];
        p2s[i] = pk2(p, p);
    }
    __syncthreads();

    ull acc[NH];
    #pragma unroll
    for (int h = 0; h < NH; ++h) acc[h] = 0ULL;

    const ull* xq = (const ull*)(x + ((size_t)n*LSEQ + s*256)*DM) + t;

    for (int r = 0; r < 256; r += 4) {
        ull x0 = xq[(size_t)(r+0)*(DM/2)];
        ull x1 = xq[(size_t)(r+1)*(DM/2)];
        ull x2 = xq[(size_t)(r+2)*(DM/2)];
        ull x3 = xq[(size_t)(r+3)*(DM/2)];
        #pragma unroll
        for (int h = 0; h < NH; ++h) {
            const ulonglong2* pp = (const ulonglong2*)(p2s + h*256 + r);
            ulonglong2 p01 = pp[0];
            ulonglong2 p23 = pp[1];
            fma2(acc[h], p01.x, x0);
            fma2(acc[h], p01.y, x1);
            fma2(acc[h], p23.x, x2);
            fma2(acc[h], p23.y, x3);
        }
    }
    #pragma unroll
    for (int h = 0; h < NH; ++h)
        g_part[(((size_t)(n*NCH + s)*NH) + h)*(DM/2) + t] = acc[h];
}

// ------------------------------ merge -> xbar[n][h][d] -----------------------
__global__ void k_merge() {
    int h = blockIdx.x, n = blockIdx.y, t = threadIdx.x;
    const float* pf = (const float*)g_part;
    #pragma unroll
    for (int j = 0; j < 3; ++j) {
        int d = j*256 + t;
        float a = 0.f;
        #pragma unroll
        for (int s = 0; s < NCH; ++s)
            a += pf[(((size_t)(n*NCH + s)*NH) + h)*DM + d];
        g_xbar[((size_t)n*NH + h)*DM + d] = a;
    }
}

// ------------------------------ proj1: o = xbar@wv + bv ----------------------
// grid (3, NB), block 256.
__global__ void k_proj1(const float* __restrict__ wv, const float* __restrict__ bv) {
    int n = blockIdx.y, he = blockIdx.x*256 + threadIdx.x;
    int h = he >> 6;
    const float* xh = g_xbar + ((size_t)n*NH + h)*DM;
    float a = bv[he];
    #pragma unroll 8
    for (int d = 0; d < DM; ++d) a = fmaf(xh[d], wv[(size_t)d*(NH*DH) + he], a);
    g_o[(size_t)n*(NH*DH) + he] = a;
}

// ------------------------------ proj2 + LN (fused) ---------------------------
// grid (NB), block 768. xa = o@wo + bo; y = LN(xa).
__global__ void k_proj2ln(const float* __restrict__ wo, const float* __restrict__ bo,
                          const float* __restrict__ ln_s, const float* __restrict__ ln_b) {
    __shared__ float o_s[NH*DH];
    __shared__ float red[768];
    int n = blockIdx.x, t = threadIdx.x;
    o_s[t] = g_o[(size_t)n*(NH*DH) + t];
    __syncthreads();
    float a = bo[t];
    #pragma unroll 8
    for (int he = 0; he < NH*DH; ++he) a = fmaf(o_s[he], wo[(size_t)he*DM + t], a);
    g_xa[(size_t)n*DM + t] = a;
    // LayerNorm across the 768 threads
    red[t] = a; __syncthreads();
    if (t < 256) red[t] = red[t] + red[t+256] + red[t+512];
    __syncthreads();
    for (int s = 128; s > 0; s >>= 1) { if (t < s) red[t] += red[t+s]; __syncthreads(); }
    float mu = red[0] * (1.f/DM);
    __syncthreads();
    float dd = a - mu;
    red[t] = dd*dd; __syncthreads();
    if (t < 256) red[t] = red[t] + red[t+256] + red[t+512];
    __syncthreads();
    for (int s = 128; s > 0; s >>= 1) { if (t < s) red[t] += red[t+s]; __syncthreads(); }
    float rstd = rsqrtf(red[0] * (1.f/DM) + 1e-6f);
    g_y[(size_t)n*DM + t] = dd * rstd * ln_s[t] + ln_b[t];
}

// ------------------------------ MLP1: h1 = gelu(y@w1 + b1) -------------------
// grid (12, NB), block 256.
__global__ void map_mlp1(const float* __restrict__ w1, const float* __restrict__ b1) {
    __shared__ float y_s[DM];
    int n = blockIdx.y, bj = blockIdx.x, t = threadIdx.x;
    for (int j = 0; j < 3; ++j) y_s[j*256 + t] = g_y[(size_t)n*DM + j*256 + t];
    __syncthreads();
    int k = bj*256 + t;
    float a = b1[k];
    #pragma unroll 8
    for (int d = 0; d < DM; ++d) a = fmaf(y_s[d], w1[(size_t)d*MLPD + k], a);
    float u = 0.7978845608028654f * (a + 0.044715f * a * a * a);
    g_h1[(size_t)n*MLPD + k] = 0.5f * a * (1.f + tanhf(u));
}

// ------------------------------ MLP2 partial: K-split 4 ----------------------
// grid (3, NB, 4), block 256.
__global__ void k_mlp2p(const float* __restrict__ w2) {
    __shared__ float h1_s[MLPD/4];
    int n = blockIdx.y, bj = blockIdx.x, kc = blockIdx.z, t = threadIdx.x;
    for (int i = t; i < MLPD/4; i += 256)
        h1_s[i] = g_h1[(size_t)n*MLPD + kc*(MLPD/4) + i];
    __syncthreads();
    int d = bj*256 + t;
    float a = 0.f;
    #pragma unroll 8
    for (int k = 0; k < MLPD/4; ++k)
        a = fmaf(h1_s[k], w2[(size_t)(kc*(MLPD/4) + k)*DM + d], a);
    g_mp[((size_t)kc*NB + n)*DM + d] = a;
}

// ------------------------------ final ----------------------------------------
// grid (3, NB), block 256.
__global__ void k_final(const float* __restrict__ b2, float* __restrict__ out) {
    int d = blockIdx.x*256 + threadIdx.x, n = blockIdx.y;
    float a = g_xa[(size_t)n*DM + d] + b2[d];
    #pragma unroll
    for (int kc = 0; kc < 4; ++kc)
        a += g_mp[((size_t)kc*NB + n)*DM + d];
    out[(size_t)n*DM + d] = a;
}

// ------------------------------ launcher -------------------------------------
extern "C" void kernel_launch(void* const* d_in, const int* in_sizes, int n_in,
                              void* d_out, int out_size) {
    const float* x     = (const float*)d_in[0];
    const float* probe = (const float*)d_in[1];
    const float* wq    = (const float*)d_in[2];
    const float* bq    = (const float*)d_in[3];
    const float* wk    = (const float*)d_in[4];
    const float* wv    = (const float*)d_in[6];
    const float* bv    = (const float*)d_in[7];
    const float* wo    = (const float*)d_in[8];
    const float* bo    = (const float*)d_in[9];
    const float* ln_s  = (const float*)d_in[10];
    const float* ln_b  = (const float*)d_in[11];
    const float* w1    = (const float*)d_in[12];
    const float* b1    = (const float*)d_in[13];
    const float* w2    = (const float*)d_in[14];
    const float* b2    = (const float*)d_in[15];
    float* out = (float*)d_out;

    k_qp<<<4, DM>>>(probe, wq);                            // 1
    k_qc<<<1, DM>>>(bq);                                   // 2
    prep_wkq<<<(NH*DM + 255)/256, 256>>>(wk);              // 3
    k_logits<<<dim3(NCH, NB), 256>>>(x);                   // 4 <- profiled
    k_xbar<<<dim3(NCH, NB), 384>>>(x);                     // 5
    k_merge<<<dim3(NH, NB), 256>>>();                      // 6
    k_proj1<<<dim3(3, NB), 256>>>(wv, bv);                 // 7
    k_proj2ln<<<NB, 768>>>(wo, bo, ln_s, ln_b);            // 8
    map_mlp1<<<dim3(MLPD/256, NB), 256>>>(w1, b1);         // 9
    k_mlp2p<<<dim3(3, NB, 4), 256>>>(w2);                  // 10
    k_final<<<dim3(3, NB), 256>>>(b2, out);                // 11
}

// round 14
// speedup vs baseline: 1.1178x; 1.1178x over previous
#include <cuda_runtime.h>
#include <math.h>

typedef unsigned long long ull;

// ---------------------------------------------------------------------------
// MAPHead: probe-attention pooling + MLP. N=32, L=4096, D=768, H=12, MLP=3072.
//   logits[n,h,l] = x[n,l,:] . wkq[:,h]      (pass 1, f32x2 head pairs, 2-row;
//                                             bk.q const dropped: softmax-inv)
//   k_logits emits per-chunk (m,sumexp)      (fused normalizer, parallel tail)
//   xbar[n,h,:] = sum_l softmax * x[n,l,:]   (pass 2, f32x2, 2 cols/thread)
//   o -> xa+LN (fused) -> MLP on [32,768]    (epilogue GEMVs, mlp2 K-split)
// ---------------------------------------------------------------------------

#define NB   32
#define LSEQ 4096
#define DM   768
#define NH   12
#define DH   64
#define MLPD 3072
#define NCH  16                 // 256-row chunks (pass 1 & 2)

__device__ __forceinline__ ull pk2(float a, float b) {
    ull r; asm("mov.b64 %0,{%1,%2};" : "=l"(r) : "f"(a), "f"(b)); return r;
}
__device__ __forceinline__ void up2(ull v, float& a, float& b) {
    asm("mov.b64 {%0,%1},%2;" : "=f"(a), "=f"(b) : "l"(v));
}
__device__ __forceinline__ void fma2(ull& acc, ull a, ull b) {
    asm("fma.rn.f32x2 %0,%1,%2,%0;" : "+l"(acc) : "l"(a), "l"(b));
}
__device__ __forceinline__ ull add2(ull a, ull b) {
    ull r; asm("add.rn.f32x2 %0,%1,%2;" : "=l"(r) : "l"(a), "l"(b)); return r;
}

// ------------------------------ scratch -------------------------------------
__device__ float  g_qp[4*DM];                         // probe@wq d-slice partials
__device__ float2 g_wkq2[6*DM];                       // [hp][d] head pairs
__device__ float  g_logits[(size_t)NB*NH*LSEQ];
__device__ float2 g_cms[NB*NCH*NH];                   // per-chunk (m, sumexp)
__device__ ull    g_part[(size_t)NB*NCH*NH*(DM/2)];   // chunk partial xbar
__device__ float  g_xbar[NB*NH*DM];
__device__ float  g_o[NB*NH*DH];
__device__ float  g_xa[NB*DM];
__device__ float  g_y[NB*DM];
__device__ float  g_h1[NB*MLPD];
__device__ float  g_mp[4*NB*DM];                      // mlp2 K-split partials

// ------------------------------ prep 1: qp[s][he] = probe_s . wq_s -----------
// grid 4 (d-slices of 192), block 768 (he). wq[d*768+he]: coalesced.
__global__ void k_qp(const float* __restrict__ probe,
                     const float* __restrict__ wq) {
    __shared__ float ps[192];
    int s = blockIdx.x, t = threadIdx.x;
    if (t < 192) ps[t] = probe[s*192 + t];
    __syncthreads();
    float acc = 0.f;
    const float* wp = wq + (size_t)(s*192)*(NH*DH) + t;
    #pragma unroll 8
    for (int d = 0; d < 192; ++d) acc = fmaf(ps[d], wp[(size_t)d*(NH*DH)], acc);
    g_qp[s*DM + t] = acc;
}

// ------------------------------ prep 2: wkq (qvec fused, head-pair packed) ---
// grid 36, block 256. Each block rebuilds qvec in smem (cheap, removes a launch).
__global__ void prep_wkq(const float* __restrict__ wk, const float* __restrict__ bq) {
    __shared__ float qv[NH*DH];
    int t = threadIdx.x;
    for (int i = t; i < NH*DH; i += 256)
        qv[i] = (g_qp[i] + g_qp[DM + i] + g_qp[2*DM + i] + g_qp[3*DM + i]
                 + bq[i]) * 0.125f;
    __syncthreads();
    int idx = blockIdx.x*256 + t;
    if (idx < NH*DM) {
        int d = idx / NH, h = idx - d*NH;
        float acc = 0.f;
        const float* w = wk + (size_t)d*(NH*DH) + h*DH;
        const float* q = qv + h*DH;
        #pragma unroll
        for (int e = 0; e < DH; ++e) acc = fmaf(w[e], q[e], acc);
        ((float*)g_wkq2)[(((h>>1)*DM) + d)*2 + (h&1)] = acc;
    }
}

// ------------------------------ pass 1: logits + chunk (m,s) -----------------
// grid (NCH, NB), block 256 (8 warps). Warp: 32 rows, 2 at a time (R11-proven).
// Tail: 192 threads (16 per head), shfl-reduced (m, sumexp).
__global__ void __launch_bounds__(256, 4)
k_logits(const float* __restrict__ x) {
    __shared__ float2 wks[6*DM];     // 36 KB
    const int t = threadIdx.x, lane = t & 31, w = t >> 5;
    const int n = blockIdx.y;
    const int row0 = blockIdx.x*256 + w*32;

    for (int i = t; i < 6*DM/2; i += 256)
        ((float4*)wks)[i] = ((const float4*)g_wkq2)[i];
    __syncthreads();

    for (int rb = 0; rb < 32; rb += 2) {
        const float* x0 = x + ((size_t)n*LSEQ + row0 + rb)*DM + lane;
        const float* x1 = x0 + DM;
        ull a0[6], a1[6];
        #pragma unroll
        for (int hp = 0; hp < 6; ++hp) { a0[hp] = 0ULL; a1[hp] = 0ULL; }

        #pragma unroll 4
        for (int j = 0; j < 24; ++j) {
            float u = x0[j*32];
            float v = x1[j*32];
            ull U = pk2(u, u), V = pk2(v, v);
            #pragma unroll
            for (int hp = 0; hp < 6; ++hp) {
                ull wv = *(const ull*)(wks + hp*DM + j*32 + lane);
                fma2(a0[hp], U, wv);
                fma2(a1[hp], V, wv);
            }
        }

        // packed butterfly reduce: 2 SHFL + 1 ADD2 per (hp, step)
        #pragma unroll
        for (int off = 16; off; off >>= 1)
            #pragma unroll
            for (int hp = 0; hp < 6; ++hp) {
                a0[hp] = add2(a0[hp], __shfl_xor_sync(0xffffffffu, a0[hp], off));
                a1[hp] = add2(a1[hp], __shfl_xor_sync(0xffffffffu, a1[hp], off));
            }

        if (lane < 2) {
            int l = row0 + rb + lane;
            float fr[NH];
            #pragma unroll
            for (int hp = 0; hp < 6; ++hp) {
                ull a = (lane == 0) ? a0[hp] : a1[hp];
                up2(a, fr[2*hp], fr[2*hp+1]);
            }
            #pragma unroll
            for (int h = 0; h < NH; ++h)
                g_logits[((size_t)n*NH + h)*LSEQ + l] = fr[h];
        }
    }

    // tail: per-chunk (m, sumexp), 16 threads per head, shfl-reduced
    __syncthreads();
    if (t < 192) {
        int g = t >> 4, i = t & 15;
        const float* lp = g_logits + ((size_t)n*NH + g)*LSEQ + blockIdx.x*256;
        float m = -1e30f;
        #pragma unroll
        for (int k = 0; k < 16; ++k) m = fmaxf(m, lp[i + k*16]);
        #pragma unroll
        for (int off = 8; off; off >>= 1)
            m = fmaxf(m, __shfl_xor_sync(0xffffffffu, m, off));
        float s = 0.f;
        #pragma unroll
        for (int k = 0; k < 16; ++k) s += __expf(lp[i + k*16] - m);
        #pragma unroll
        for (int off = 8; off; off >>= 1)
            s += __shfl_xor_sync(0xffffffffu, s, off);
        if (i == 0)
            g_cms[((size_t)n*NCH + blockIdx.x)*NH + g] = make_float2(m, s);
    }
}

// ------------------------------ pass 2: xbar (frozen) ------------------------
__global__ void __launch_bounds__(384)
k_xbar(const float* __restrict__ x) {
    __shared__ ull   p2s[NH*256];    // 24 KB
    __shared__ float Ms[NH], Is[NH];
    const int t = threadIdx.x, s = blockIdx.x, n = blockIdx.y;

    if (t < NH) {
        float M = -1e30f;
        #pragma unroll
        for (int c = 0; c < NCH; ++c)
            M = fmaxf(M, g_cms[((size_t)n*NCH + c)*NH + t].x);
        float S = 0.f;
        #pragma unroll
        for (int c = 0; c < NCH; ++c) {
            float2 ms = g_cms[((size_t)n*NCH + c)*NH + t];
            S += __expf(ms.x - M) * ms.y;
        }
        Ms[t] = M; Is[t] = 1.f / S;
    }
    __syncthreads();

    for (int i = t; i < NH*256; i += 384) {
        int h = i >> 8, r = i & 255;
        float lg = g_logits[((size_t)n*NH + h)*LSEQ + s*256 + r];
        float p = __expf(lg - Ms[h]) * Is[h];
        p2s[i] = pk2(p, p);
    }
    __syncthreads();

    ull acc[NH];
    #pragma unroll
    for (int h = 0; h < NH; ++h) acc[h] = 0ULL;

    const ull* xq = (const ull*)(x + ((size_t)n*LSEQ + s*256)*DM) + t;

    for (int r = 0; r < 256; r += 4) {
        ull x0 = xq[(size_t)(r+0)*(DM/2)];
        ull x1 = xq[(size_t)(r+1)*(DM/2)];
        ull x2 = xq[(size_t)(r+2)*(DM/2)];
        ull x3 = xq[(size_t)(r+3)*(DM/2)];
        #pragma unroll
        for (int h = 0; h < NH; ++h) {
            const ulonglong2* pp = (const ulonglong2*)(p2s + h*256 + r);
            ulonglong2 p01 = pp[0];
            ulonglong2 p23 = pp[1];
            fma2(acc[h], p01.x, x0);
            fma2(acc[h], p01.y, x1);
            fma2(acc[h], p23.x, x2);
            fma2(acc[h], p23.y, x3);
        }
    }
    #pragma unroll
    for (int h = 0; h < NH; ++h)
        g_part[(((size_t)(n*NCH + s)*NH) + h)*(DM/2) + t] = acc[h];
}

// ------------------------------ merge -> xbar[n][h][d] -----------------------
__global__ void k_merge() {
    int h = blockIdx.x, n = blockIdx.y, t = threadIdx.x;
    const float* pf = (const float*)g_part;
    #pragma unroll
    for (int j = 0; j < 3; ++j) {
        int d = j*256 + t;
        float a = 0.f;
        #pragma unroll
        for (int s = 0; s < NCH; ++s)
            a += pf[(((size_t)(n*NCH + s)*NH) + h)*DM + d];
        g_xbar[((size_t)n*NH + h)*DM + d] = a;
    }
}

// ------------------------------ proj1: o = xbar@wv + bv ----------------------
// grid (3, NB), block 256.
__global__ void k_proj1(const float* __restrict__ wv, const float* __restrict__ bv) {
    int n = blockIdx.y, he = blockIdx.x*256 + threadIdx.x;
    int h = he >> 6;
    const float* xh = g_xbar + ((size_t)n*NH + h)*DM;
    float a = bv[he];
    #pragma unroll 8
    for (int d = 0; d < DM; ++d) a = fmaf(xh[d], wv[(size_t)d*(NH*DH) + he], a);
    g_o[(size_t)n*(NH*DH) + he] = a;
}

// ------------------------------ proj2 + LN (fused) ---------------------------
// grid (NB), block 768. xa = o@wo + bo; y = LN(xa).
__global__ void k_proj2ln(const float* __restrict__ wo, const float* __restrict__ bo,
                          const float* __restrict__ ln_s, const float* __restrict__ ln_b) {
    __shared__ float o_s[NH*DH];
    __shared__ float red[768];
    int n = blockIdx.x, t = threadIdx.x;
    o_s[t] = g_o[(size_t)n*(NH*DH) + t];
    __syncthreads();
    float a = bo[t];
    #pragma unroll 8
    for (int he = 0; he < NH*DH; ++he) a = fmaf(o_s[he], wo[(size_t)he*DM + t], a);
    g_xa[(size_t)n*DM + t] = a;
    // LayerNorm across the 768 threads
    red[t] = a; __syncthreads();
    if (t < 256) red[t] = red[t] + red[t+256] + red[t+512];
    __syncthreads();
    for (int s = 128; s > 0; s >>= 1) { if (t < s) red[t] += red[t+s]; __syncthreads(); }
    float mu = red[0] * (1.f/DM);
    __syncthreads();
    float dd = a - mu;
    red[t] = dd*dd; __syncthreads();
    if (t < 256) red[t] = red[t] + red[t+256] + red[t+512];
    __syncthreads();
    for (int s = 128; s > 0; s >>= 1) { if (t < s) red[t] += red[t+s]; __syncthreads(); }
    float rstd = rsqrtf(red[0] * (1.f/DM) + 1e-6f);
    g_y[(size_t)n*DM + t] = dd * rstd * ln_s[t] + ln_b[t];
}

// ------------------------------ MLP1: h1 = gelu(y@w1 + b1) -------------------
// grid (12, NB), block 256.
__global__ void map_mlp1(const float* __restrict__ w1, const float* __restrict__ b1) {
    __shared__ float y_s[DM];
    int n = blockIdx.y, bj = blockIdx.x, t = threadIdx.x;
    for (int j = 0; j < 3; ++j) y_s[j*256 + t] = g_y[(size_t)n*DM + j*256 + t];
    __syncthreads();
    int k = bj*256 + t;
    float a = b1[k];
    #pragma unroll 8
    for (int d = 0; d < DM; ++d) a = fmaf(y_s[d], w1[(size_t)d*MLPD + k], a);
    float u = 0.7978845608028654f * (a + 0.044715f * a * a * a);
    g_h1[(size_t)n*MLPD + k] = 0.5f * a * (1.f + tanhf(u));
}

// ------------------------------ MLP2 partial: K-split 4 ----------------------
// grid (3, NB, 4), block 256.
__global__ void k_mlp2p(const float* __restrict__ w2) {
    __shared__ float h1_s[MLPD/4];
    int n = blockIdx.y, bj = blockIdx.x, kc = blockIdx.z, t = threadIdx.x;
    for (int i = t; i < MLPD/4; i += 256)
        h1_s[i] = g_h1[(size_t)n*MLPD + kc*(MLPD/4) + i];
    __syncthreads();
    int d = bj*256 + t;
    float a = 0.f;
    #pragma unroll 8
    for (int k = 0; k < MLPD/4; ++k)
        a = fmaf(h1_s[k], w2[(size_t)(kc*(MLPD/4) + k)*DM + d], a);
    g_mp[((size_t)kc*NB + n)*DM + d] = a;
}

// ------------------------------ final ----------------------------------------
// grid (3, NB), block 256.
__global__ void k_final(const float* __restrict__ b2, float* __restrict__ out) {
    int d = blockIdx.x*256 + threadIdx.x, n = blockIdx.y;
    float a = g_xa[(size_t)n*DM + d] + b2[d];
    #pragma unroll
    for (int kc = 0; kc < 4; ++kc)
        a += g_mp[((size_t)kc*NB + n)*DM + d];
    out[(size_t)n*DM + d] = a;
}

// ------------------------------ launcher -------------------------------------
extern "C" void kernel_launch(void* const* d_in, const int* in_sizes, int n_in,
                              void* d_out, int out_size) {
    const float* x     = (const float*)d_in[0];
    const float* probe = (const float*)d_in[1];
    const float* wq    = (const float*)d_in[2];
    const float* bq    = (const float*)d_in[3];
    const float* wk    = (const float*)d_in[4];
    const float* wv    = (const float*)d_in[6];
    const float* bv    = (const float*)d_in[7];
    const float* wo    = (const float*)d_in[8];
    const float* bo    = (const float*)d_in[9];
    const float* ln_s  = (const float*)d_in[10];
    const float* ln_b  = (const float*)d_in[11];
    const float* w1    = (const float*)d_in[12];
    const float* b1    = (const float*)d_in[13];
    const float* w2    = (const float*)d_in[14];
    const float* b2    = (const float*)d_in[15];
    float* out = (float*)d_out;

    k_qp<<<4, DM>>>(probe, wq);                            // 1
    prep_wkq<<<(NH*DM + 255)/256, 256>>>(wk, bq);          // 2
    k_logits<<<dim3(NCH, NB), 256>>>(x);                   // 3
    k_xbar<<<dim3(NCH, NB), 384>>>(x);                     // 4 <- profiled
    k_merge<<<dim3(NH, NB), 256>>>();                      // 5
    k_proj1<<<dim3(3, NB), 256>>>(wv, bv);                 // 6
    k_proj2ln<<<NB, 768>>>(wo, bo, ln_s, ln_b);            // 7
    map_mlp1<<<dim3(MLPD/256, NB), 256>>>(w1, b1);         // 8
    k_mlp2p<<<dim3(3, NB, 4), 256>>>(w2);                  // 9
    k_final<<<dim3(3, NB), 256>>>(b2, out);                // 10
}